// round 15
// baseline (speedup 1.0000x reference)
#include <cuda_runtime.h>
#include <cuda_fp16.h>
#include <math.h>
#include <stdint.h>

// ---------------- problem constants ----------------
#define BB 4
#define SS 4096
#define DD 1024
#define KW 4
#define MM (BB * SS)      // 16384
#define N1 (2 * DD)       // 2048
#define EPSV 1e-6f
#define LCH 32            // scan chunk length
#define NCH (SS / LCH)    // 128
#define NKT (DD / 16)     // 64 fragment k-tiles

// ---------------- scratch (__device__ globals; no allocs) ----------------
__device__ uint32_t g_h  [(size_t)MM * DD / 2];   // rmsnorm(x) / gated y (FM16)
__device__ __half   g_xz [(size_t)MM * N1];       // GEMM1 out (fp16 row-major)
__device__ __half   g_hs [(size_t)MM * DD];       // local scan out (fp16)
__device__ uint32_t g_wt1[(size_t)N1 * DD / 2];   // in_w^T  FM16
__device__ uint32_t g_wt2[(size_t)DD * DD / 2];   // out_w^T FM16
__device__ float g_last[(size_t)BB * NCH * DD];
__device__ float g_sin [(size_t)BB * NCH * DD];
__device__ float g_l2a [DD];                      // log2(sigmoid(decay))

// FM16 A-type X[R][K] (m16n8k16 .row operand), 32-bit words:
//   word = ((rt*(K/16)+kt)*32 + (r&7)*4 + ((k&7)>>1))*4 + ((r>>3)&1) + 2*((k&15)>=8), half=k&1
// FM16 B-type Bt[N][K] (.col operand):
//   word = ((nt*(K/16)+kt)*32 + (n&7)*4 + ((k&7)>>1))*2 + ((k&15)>>3), half=k&1

// ---------------- helpers ----------------
__device__ __forceinline__ float silu_f(float v) { return v / (1.f + __expf(-v)); }

__device__ __forceinline__ uint32_t smem_u32(const void* p) {
    uint32_t a;
    asm("{ .reg .u64 t; cvta.to.shared.u64 t, %1; cvt.u32.u64 %0, t; }" : "=r"(a) : "l"(p));
    return a;
}
__device__ __forceinline__ void cp16(uint32_t s, const void* g) {
    asm volatile("cp.async.cg.shared.global [%0], [%1], 16;" :: "r"(s), "l"(g) : "memory");
}
__device__ __forceinline__ void cp_commit() {
    asm volatile("cp.async.commit_group;" ::: "memory");
}
__device__ __forceinline__ void cp_wait1() {
    asm volatile("cp.async.wait_group 1;" ::: "memory");
}
__device__ __forceinline__ void cp_wait0() {
    asm volatile("cp.async.wait_group 0;" ::: "memory");
}

__device__ __forceinline__ void mma_f16(float* c, const uint32_t* a, uint32_t b0, uint32_t b1) {
    asm volatile(
        "mma.sync.aligned.m16n8k16.row.col.f32.f16.f16.f32 "
        "{%0,%1,%2,%3}, {%4,%5,%6,%7}, {%8,%9}, {%0,%1,%2,%3};"
        : "+f"(c[0]), "+f"(c[1]), "+f"(c[2]), "+f"(c[3])
        : "r"(a[0]), "r"(a[1]), "r"(a[2]), "r"(a[3]), "r"(b0), "r"(b1));
}

__device__ __forceinline__ uint32_t pack_h2(float lo, float hi) {
    __half2 h = __floats2half2_rn(lo, hi);
    return *(uint32_t*)&h;
}

__device__ __forceinline__ float warp_reduce_sum(float v) {
    #pragma unroll
    for (int o = 16; o > 0; o >>= 1) v += __shfl_xor_sync(0xffffffffu, v, o);
    return v;
}

// ---------------- weight transpose -> FM16 B layout (both weights, one launch) --
__global__ __launch_bounds__(256) void transpose_kernel(
    const float* __restrict__ in1, __half* __restrict__ out1,
    const float* __restrict__ in2, __half* __restrict__ out2)
{
    const float* in;
    __half* out;
    int Nn;
    if (blockIdx.z == 0) { in = in1; out = out1; Nn = N1; }
    else {
        if (blockIdx.x >= DD / 32) return;
        in = in2; out = out2; Nn = DD;
    }
    __shared__ float tile[32][33];
    int n0 = blockIdx.x * 32, k0 = blockIdx.y * 32;
    int tx = threadIdx.x & 31, ty = threadIdx.x >> 5;
    #pragma unroll
    for (int i = 0; i < 32; i += 8)
        tile[ty + i][tx] = in[(size_t)(k0 + ty + i) * Nn + n0 + tx];
    __syncthreads();
    int k = k0 + tx;
    int kt = k >> 4, kk = k & 15;
    int fc = (kk & 7) >> 1, hi = kk >> 3, lo = kk & 1;
    #pragma unroll
    for (int i = 0; i < 32; i += 8) {
        int n = n0 + ty + i;
        int nt = n >> 3, fn = n & 7;
        size_t hoff = (((size_t)(nt * NKT + kt) * 32 + fn * 4 + fc) * 2 + hi) * 2 + lo;
        out[hoff] = __float2half_rn(tile[tx][ty + i]);
    }
}

// ---------------- rmsnorm, warp-per-row (fp16 FM16 A output) ----------------
__global__ __launch_bounds__(256) void rmsnorm_kernel(
    const float* __restrict__ x, const float* __restrict__ w, uint32_t* __restrict__ out)
{
    int warp = threadIdx.x >> 5, lane = threadIdx.x & 31;
    size_t row = (size_t)blockIdx.x * 8 + warp;
    const float4* xr = (const float4*)(x + row * DD);

    float4 v[8];
    float ss = 0.f;
    #pragma unroll
    for (int j = 0; j < 8; j++) {
        v[j] = xr[j * 32 + lane];
        ss += v[j].x * v[j].x + v[j].y * v[j].y + v[j].z * v[j].z + v[j].w * v[j].w;
    }
    ss = warp_reduce_sum(ss);
    float s = rsqrtf(ss * (1.f / DD) + EPSV);

    int rt = (int)(row >> 4), fr = (int)(row & 7), rh = (int)((row >> 3) & 1);
    #pragma unroll
    for (int j = 0; j < 8; j++) {
        float4 wv = ((const float4*)w)[j * 32 + lane];
        int c0 = (j * 32 + lane) * 4;
        int kt = c0 >> 4, kk = c0 & 15, hi = kk >> 3, fc0 = (kk & 7) >> 1;
        size_t wb = ((size_t)(rt * NKT + kt) * 32 + fr * 4 + fc0) * 4 + rh + 2 * hi;
        out[wb]     = pack_h2(v[j].x * s * wv.x, v[j].y * s * wv.y);
        out[wb + 4] = pack_h2(v[j].z * s * wv.z, v[j].w * s * wv.w);
    }
}

// ---------------- fp16 mma.sync GEMM (FM16 inputs) ----------------
// Block 128x128, BK=64 (4 k-tiles), 3-stage cp.async, 8 warps (4m x 2n),
// warp tile 32x64, 2 CTA/SM (4 warps/SMSP), single barrier per k-chunk.
// resid == null  -> C is fp16 (__half, row-major Nn)
// resid != null  -> C is fp32, C = acc + rs*resid
#define BKK 64
#define STG_WORDS 8192                     // A 4096 + B 4096 uint32
#define GSTG 3
#define GEMM_SMEM (GSTG * STG_WORDS * 4)   // 98304 B

__global__ __launch_bounds__(256, 2) void gemm_tc_kernel(
    int Nn, const uint32_t* __restrict__ A, const uint32_t* __restrict__ Bt,
    void* __restrict__ Cv,
    const float* __restrict__ resid, const float* __restrict__ rs_ptr)
{
    extern __shared__ float sm[];
    const int tid = threadIdx.x, lane = tid & 31, wid = tid >> 5;
    const int mtile = blockIdx.y * 128, ntile = blockIdx.x * 128;
    const int wmt = (wid & 3) * 2;      // A 16-row tile base (2 tiles per warp)
    const int wnt = (wid >> 2) * 8;     // B 8-col tile base  (8 tiles per warp)

    uint32_t smb = smem_u32(sm);

    // flat loaders: A 4096 words = 8 rt-blocks x 512; B 4096 words = 16 nt-blocks x 256
    auto stage_load = [&](int s, int kc) {
        uint32_t as = smb + (uint32_t)s * (STG_WORDS * 4);
        uint32_t bs = as + 4096 * 4;
        #pragma unroll
        for (int i = 0; i < 4; i++) {
            int idx = i * 1024 + tid * 4;
            int rt = idx >> 9, w = idx & 511;
            cp16(as + (uint32_t)idx * 4,
                 A + (size_t)(blockIdx.y * 8 + rt) * (NKT * 128) + kc * 512 + w);
        }
        #pragma unroll
        for (int i = 0; i < 4; i++) {
            int idx = i * 1024 + tid * 4;
            int nt = idx >> 8, w = idx & 255;
            cp16(bs + (uint32_t)idx * 4,
                 Bt + (size_t)(blockIdx.x * 16 + nt) * (NKT * 64) + kc * 256 + w);
        }
        cp_commit();
    };

    float acc[2][8][4];
    #pragma unroll
    for (int mi = 0; mi < 2; mi++)
        #pragma unroll
        for (int ni = 0; ni < 8; ni++)
            #pragma unroll
            for (int j = 0; j < 4; j++) acc[mi][ni][j] = 0.f;

    const int NKC = DD / BKK;           // 16
    stage_load(0, 0);
    stage_load(1, 1);

    for (int kc = 0; kc < NKC; kc++) {
        cp_wait1();
        __syncthreads();                 // single barrier per chunk
        if (kc + 2 < NKC) stage_load((kc + 2) % GSTG, kc + 2);
        else cp_commit();

        const uint32_t* sA = (const uint32_t*)sm + (kc % GSTG) * STG_WORDS;
        const uint32_t* sB = sA + 4096;

        #pragma unroll
        for (int kt = 0; kt < 4; kt++) {
            uint32_t a[2][4];
            #pragma unroll
            for (int mi = 0; mi < 2; mi++) {
                uint4 av = *(const uint4*)(sA + (((wmt + mi) * 4 + kt) * 32 + lane) * 4);
                a[mi][0] = av.x; a[mi][1] = av.y; a[mi][2] = av.z; a[mi][3] = av.w;
            }
            #pragma unroll
            for (int ni = 0; ni < 8; ni++) {
                uint2 bv = *(const uint2*)(sB + (((wnt + ni) * 4 + kt) * 32 + lane) * 2);
                #pragma unroll
                for (int mi = 0; mi < 2; mi++)
                    mma_f16(acc[mi][ni], a[mi], bv.x, bv.y);
            }
        }
    }
    cp_wait0();

    // epilogue
    const int fr = lane >> 2, fc = lane & 3;
    const int wm = (wid & 3) * 32, wn = (wid >> 2) * 64;
    if (resid) {
        float* C = (float*)Cv;
        float rs = __ldg(rs_ptr);
        #pragma unroll
        for (int mi = 0; mi < 2; mi++)
            #pragma unroll
            for (int half = 0; half < 2; half++) {
                int row = mtile + wm + mi * 16 + half * 8 + fr;
                #pragma unroll
                for (int ni = 0; ni < 8; ni++) {
                    int col = ntile + wn + ni * 8 + fc * 2;
                    size_t off = (size_t)row * Nn + col;
                    float2 rv = *(const float2*)(resid + off);
                    float2 v = make_float2(fmaf(rs, rv.x, acc[mi][ni][half * 2]),
                                           fmaf(rs, rv.y, acc[mi][ni][half * 2 + 1]));
                    *(float2*)(C + off) = v;
                }
            }
    } else {
        uint32_t* Ch = (uint32_t*)Cv;   // fp16 output, 2 cols per word
        #pragma unroll
        for (int mi = 0; mi < 2; mi++)
            #pragma unroll
            for (int half = 0; half < 2; half++) {
                int row = mtile + wm + mi * 16 + half * 8 + fr;
                #pragma unroll
                for (int ni = 0; ni < 8; ni++) {
                    int col = ntile + wn + ni * 8 + fc * 2;
                    Ch[(size_t)row * (Nn / 2) + col / 2] =
                        pack_h2(acc[mi][ni][half * 2], acc[mi][ni][half * 2 + 1]);
                }
            }
    }
}

// ---------------- scan phase 1: local conv+silu+scan, 2 channels/thread -------
__global__ __launch_bounds__(256) void conv_local_kernel(
    const __half* __restrict__ xz, const float* __restrict__ conv_w,
    const float* __restrict__ conv_b, const float* __restrict__ decay,
    __half* __restrict__ hs, float* __restrict__ last)
{
    int idx = blockIdx.x * blockDim.x + threadIdx.x;   // BB*NCH*DD/2
    int d2 = idx % (DD / 2);                           // pair index
    int ch = (idx / (DD / 2)) % NCH;
    int b  = idx / ((DD / 2) * NCH);
    int d  = d2 * 2;

    float4 cw0 = *(const float4*)(conv_w + d * KW);        // w[d][0..3]
    float4 cw1 = *(const float4*)(conv_w + (d + 1) * KW);  // w[d+1][0..3]
    float2 bias = *(const float2*)(conv_b + d);
    float2 dc   = *(const float2*)(decay + d);
    float aA = 1.f / (1.f + __expf(-dc.x));
    float aB = 1.f / (1.f + __expf(-dc.y));

    int t0 = ch * LCH;
    const __half2* xb = (const __half2*)(xz + ((size_t)b * SS + t0) * N1) + d2;
    __half2* out = (__half2*)(hs + ((size_t)b * SS + t0) * DD) + d2;

    float x0A = 0.f, x1A = 0.f, x2A = 0.f;
    float x0B = 0.f, x1B = 0.f, x2B = 0.f;
    if (ch > 0) {
        float2 p3 = __half22float2(xb[-3 * (N1 / 2)]);
        float2 p2 = __half22float2(xb[-2 * (N1 / 2)]);
        float2 p1 = __half22float2(xb[-1 * (N1 / 2)]);
        x0A = p3.x; x1A = p2.x; x2A = p1.x;
        x0B = p3.y; x1B = p2.y; x2B = p1.y;
    }
    float hA = 0.f, hB = 0.f;
    #pragma unroll 4
    for (int t = 0; t < LCH; t++) {
        float2 xt = __half22float2(xb[(size_t)t * (N1 / 2)]);
        float cA = fmaf(cw0.x, x0A, fmaf(cw0.y, x1A, fmaf(cw0.z, x2A, fmaf(cw0.w, xt.x, bias.x))));
        float cB = fmaf(cw1.x, x0B, fmaf(cw1.y, x1B, fmaf(cw1.z, x2B, fmaf(cw1.w, xt.y, bias.y))));
        cA = silu_f(cA);
        cB = silu_f(cB);
        hA = fmaf(aA, hA, cA);
        hB = fmaf(aB, hB, cB);
        out[(size_t)t * (DD / 2)] = __floats2half2_rn(hA, hB);
        x0A = x1A; x1A = x2A; x2A = xt.x;
        x0B = x1B; x1B = x2B; x2B = xt.y;
    }
    *(float2*)(last + ((size_t)b * NCH + ch) * DD + d) = make_float2(hA, hB);
}

// ---------------- scan phase 2: carry chain + l2a precompute ----------------
__global__ __launch_bounds__(256) void carry_kernel(
    const float* __restrict__ decay, const float* __restrict__ last,
    float* __restrict__ sin_, float* __restrict__ l2a)
{
    int idx = blockIdx.x * blockDim.x + threadIdx.x;   // BB*DD
    int d = idx % DD, b = idx / DD;
    float a = 1.f / (1.f + __expf(-decay[d]));
    if (b == 0) l2a[d] = log2f(a);
    float aL = a;
    #pragma unroll
    for (int i = 0; i < 5; i++) aL *= aL;              // a^32
    float c = 0.f;
    #pragma unroll 4
    for (int j = 0; j < NCH; j++) {
        size_t o = ((size_t)b * NCH + j) * DD + d;
        sin_[o] = c;
        c = fmaf(aL, c, last[o]);
    }
}

// ---------------- gated rmsnorm with fused carry, warp-per-row (FM16 out) -----
__global__ __launch_bounds__(256) void gate_kernel(
    const __half* __restrict__ hs, const float* __restrict__ gate_w,
    const __half* __restrict__ xz, const float* __restrict__ l2a,
    const float* __restrict__ sin_, uint32_t* __restrict__ y)
{
    int warp = threadIdx.x >> 5, lane = threadIdx.x & 31;
    size_t row = (size_t)blockIdx.x * 8 + warp;
    int b = (int)(row / SS);
    int sidx = (int)(row % SS);
    int chk = sidx / LCH, tt = sidx % LCH;
    float tp = (float)(tt + 1);

    const uint2* hr = (const uint2*)(hs + row * DD);
    const float4* sr = (const float4*)(sin_ + ((size_t)b * NCH + chk) * DD);
    const float4* lr = (const float4*)l2a;

    float4 v[8];
    float ss = 0.f;
    #pragma unroll
    for (int j = 0; j < 8; j++) {
        uint2 hw = hr[j * 32 + lane];
        float2 f0 = __half22float2(*(__half2*)&hw.x);
        float2 f1 = __half22float2(*(__half2*)&hw.y);
        float4 sv = sr[j * 32 + lane];
        float4 la = lr[j * 32 + lane];
        v[j].x = f0.x + sv.x * exp2f(tp * la.x);
        v[j].y = f0.y + sv.y * exp2f(tp * la.y);
        v[j].z = f1.x + sv.z * exp2f(tp * la.z);
        v[j].w = f1.y + sv.w * exp2f(tp * la.w);
        ss += v[j].x * v[j].x + v[j].y * v[j].y + v[j].z * v[j].z + v[j].w * v[j].w;
    }
    ss = warp_reduce_sum(ss);
    float s = rsqrtf(ss * (1.f / DD) + EPSV);

    const uint2* zr = (const uint2*)(xz + row * N1 + DD);
    int rt = (int)(row >> 4), fr = (int)(row & 7), rh = (int)((row >> 3) & 1);
    #pragma unroll
    for (int j = 0; j < 8; j++) {
        float4 gw = ((const float4*)gate_w)[j * 32 + lane];
        uint2 zw = zr[j * 32 + lane];
        float2 z0 = __half22float2(*(__half2*)&zw.x);
        float2 z1 = __half22float2(*(__half2*)&zw.y);
        int c0 = (j * 32 + lane) * 4;
        int kt = c0 >> 4, kk = c0 & 15, hi = kk >> 3, fc0 = (kk & 7) >> 1;
        size_t wb = ((size_t)(rt * NKT + kt) * 32 + fr * 4 + fc0) * 4 + rh + 2 * hi;
        y[wb]     = pack_h2(v[j].x * s * gw.x * silu_f(z0.x), v[j].y * s * gw.y * silu_f(z0.y));
        y[wb + 4] = pack_h2(v[j].z * s * gw.z * silu_f(z1.x), v[j].w * s * gw.w * silu_f(z1.y));
    }
}

// ---------------- host ----------------
extern "C" void kernel_launch(void* const* d_in, const int* in_sizes, int n_in,
                              void* d_out, int out_size)
{
    const float* x         = (const float*)d_in[0];
    const float* norm_w    = (const float*)d_in[1];
    const float* in_w      = (const float*)d_in[2];
    const float* conv_w    = (const float*)d_in[3];
    const float* conv_b    = (const float*)d_in[4];
    const float* decay     = (const float*)d_in[5];
    const float* gate_w    = (const float*)d_in[6];
    const float* out_w     = (const float*)d_in[7];
    const float* res_scale = (const float*)d_in[8];
    float* out = (float*)d_out;

    uint32_t *p_h, *p_wt1, *p_wt2;
    __half *p_xz, *p_hs;
    float *p_last, *p_sin, *p_l2a;
    cudaGetSymbolAddress((void**)&p_h,    g_h);
    cudaGetSymbolAddress((void**)&p_xz,   g_xz);
    cudaGetSymbolAddress((void**)&p_hs,   g_hs);
    cudaGetSymbolAddress((void**)&p_wt1,  g_wt1);
    cudaGetSymbolAddress((void**)&p_wt2,  g_wt2);
    cudaGetSymbolAddress((void**)&p_last, g_last);
    cudaGetSymbolAddress((void**)&p_sin,  g_sin);
    cudaGetSymbolAddress((void**)&p_l2a,  g_l2a);

    static bool smem_set = false;
    if (!smem_set) {
        cudaFuncSetAttribute(gemm_tc_kernel,
                             cudaFuncAttributeMaxDynamicSharedMemorySize, GEMM_SMEM);
        smem_set = true;
    }

    // 0. transpose both weights -> fp16 FM16 (one launch)
    transpose_kernel<<<dim3(N1 / 32, DD / 32, 2), 256>>>(
        in_w, (__half*)p_wt1, out_w, (__half*)p_wt2);

    // 1. h = rmsnorm(x) (fp16 FM16), warp-per-row
    rmsnorm_kernel<<<MM / 8, 256>>>(x, norm_w, p_h);

    // 2. xz = h @ in_w  (fp16 output)
    gemm_tc_kernel<<<dim3(N1 / 128, MM / 128), 256, GEMM_SMEM>>>(
        N1, p_h, p_wt1, p_xz, nullptr, nullptr);

    // 3. chunked conv + local scan (LCH=32, 2ch/thread) + carry chain
    conv_local_kernel<<<(BB * NCH * DD / 2) / 256, 256>>>(
        p_xz, conv_w, conv_b, decay, p_hs, p_last);
    carry_kernel<<<(BB * DD) / 256, 256>>>(decay, p_last, p_sin, p_l2a);

    // 4. y = rmsnorm(hs + carry)*silu(z) (fp16 FM16), warp-per-row -> g_h
    gate_kernel<<<MM / 8, 256>>>(p_hs, gate_w, p_xz, p_l2a, p_sin, p_h);

    // 5. out = res_scale*x + y @ out_w  (fp32 + residual)
    gemm_tc_kernel<<<dim3(DD / 128, MM / 128), 256, GEMM_SMEM>>>(
        DD, p_h, p_wt2, out, x, res_scale);
}

// round 16
// speedup vs baseline: 1.1410x; 1.1410x over previous
#include <cuda_runtime.h>
#include <cuda_fp16.h>
#include <math.h>
#include <stdint.h>

// ---------------- problem constants ----------------
#define BB 4
#define SS 4096
#define DD 1024
#define KW 4
#define MM (BB * SS)      // 16384
#define N1 (2 * DD)       // 2048
#define EPSV 1e-6f
#define LCH 32            // scan chunk length
#define NCH (SS / LCH)    // 128
#define NKT (DD / 16)     // 64 fragment k-tiles

// ---------------- scratch (__device__ globals; no allocs) ----------------
__device__ uint32_t g_h  [(size_t)MM * DD / 2];   // rmsnorm(x) / gated y (FM16)
__device__ __half   g_xz [(size_t)MM * N1];       // GEMM1 out (fp16 row-major)
__device__ __half   g_hs [(size_t)MM * DD];       // local scan out (fp16)
__device__ uint32_t g_wt1[(size_t)N1 * DD / 2];   // in_w^T  FM16
__device__ uint32_t g_wt2[(size_t)DD * DD / 2];   // out_w^T FM16
__device__ float g_last[(size_t)BB * NCH * DD];
__device__ float g_sin [(size_t)BB * NCH * DD];
__device__ float g_l2a [DD];                      // log2(sigmoid(decay))

// FM16 A-type X[R][K] (m16n8k16 .row operand), 32-bit words:
//   word = ((rt*(K/16)+kt)*32 + (r&7)*4 + ((k&7)>>1))*4 + ((r>>3)&1) + 2*((k&15)>=8), half=k&1
// FM16 B-type Bt[N][K] (.col operand):
//   word = ((nt*(K/16)+kt)*32 + (n&7)*4 + ((k&7)>>1))*2 + ((k&15)>>3), half=k&1

// ---------------- helpers ----------------
__device__ __forceinline__ float silu_f(float v) {
    return __fdividef(v, 1.f + __expf(-v));
}

__device__ __forceinline__ uint32_t smem_u32(const void* p) {
    uint32_t a;
    asm("{ .reg .u64 t; cvta.to.shared.u64 t, %1; cvt.u32.u64 %0, t; }" : "=r"(a) : "l"(p));
    return a;
}
__device__ __forceinline__ void cp16(uint32_t s, const void* g) {
    asm volatile("cp.async.cg.shared.global [%0], [%1], 16;" :: "r"(s), "l"(g) : "memory");
}
__device__ __forceinline__ void cp_commit() {
    asm volatile("cp.async.commit_group;" ::: "memory");
}
__device__ __forceinline__ void cp_wait1() {
    asm volatile("cp.async.wait_group 1;" ::: "memory");
}
__device__ __forceinline__ void cp_wait0() {
    asm volatile("cp.async.wait_group 0;" ::: "memory");
}

__device__ __forceinline__ void mma_f16(float* c, const uint32_t* a, uint32_t b0, uint32_t b1) {
    asm volatile(
        "mma.sync.aligned.m16n8k16.row.col.f32.f16.f16.f32 "
        "{%0,%1,%2,%3}, {%4,%5,%6,%7}, {%8,%9}, {%0,%1,%2,%3};"
        : "+f"(c[0]), "+f"(c[1]), "+f"(c[2]), "+f"(c[3])
        : "r"(a[0]), "r"(a[1]), "r"(a[2]), "r"(a[3]), "r"(b0), "r"(b1));
}

__device__ __forceinline__ uint32_t pack_h2(float lo, float hi) {
    __half2 h = __floats2half2_rn(lo, hi);
    return *(uint32_t*)&h;
}

__device__ __forceinline__ float warp_reduce_sum(float v) {
    #pragma unroll
    for (int o = 16; o > 0; o >>= 1) v += __shfl_xor_sync(0xffffffffu, v, o);
    return v;
}

// ---------------- weight transpose -> FM16 B layout (both weights, one launch) --
__global__ __launch_bounds__(256) void transpose_kernel(
    const float* __restrict__ in1, __half* __restrict__ out1,
    const float* __restrict__ in2, __half* __restrict__ out2)
{
    const float* in;
    __half* out;
    int Nn;
    if (blockIdx.z == 0) { in = in1; out = out1; Nn = N1; }
    else {
        if (blockIdx.x >= DD / 32) return;
        in = in2; out = out2; Nn = DD;
    }
    __shared__ float tile[32][33];
    int n0 = blockIdx.x * 32, k0 = blockIdx.y * 32;
    int tx = threadIdx.x & 31, ty = threadIdx.x >> 5;
    #pragma unroll
    for (int i = 0; i < 32; i += 8)
        tile[ty + i][tx] = in[(size_t)(k0 + ty + i) * Nn + n0 + tx];
    __syncthreads();
    int k = k0 + tx;
    int kt = k >> 4, kk = k & 15;
    int fc = (kk & 7) >> 1, hi = kk >> 3, lo = kk & 1;
    #pragma unroll
    for (int i = 0; i < 32; i += 8) {
        int n = n0 + ty + i;
        int nt = n >> 3, fn = n & 7;
        size_t hoff = (((size_t)(nt * NKT + kt) * 32 + fn * 4 + fc) * 2 + hi) * 2 + lo;
        out[hoff] = __float2half_rn(tile[tx][ty + i]);
    }
}

// ---------------- rmsnorm, warp-per-row (fp16 FM16 A output) ----------------
__global__ __launch_bounds__(256) void rmsnorm_kernel(
    const float* __restrict__ x, const float* __restrict__ w, uint32_t* __restrict__ out)
{
    int warp = threadIdx.x >> 5, lane = threadIdx.x & 31;
    size_t row = (size_t)blockIdx.x * 8 + warp;
    const float4* xr = (const float4*)(x + row * DD);

    float4 v[8];
    float ss = 0.f;
    #pragma unroll
    for (int j = 0; j < 8; j++) {
        v[j] = xr[j * 32 + lane];
        ss += v[j].x * v[j].x + v[j].y * v[j].y + v[j].z * v[j].z + v[j].w * v[j].w;
    }
    ss = warp_reduce_sum(ss);
    float s = rsqrtf(ss * (1.f / DD) + EPSV);

    int rt = (int)(row >> 4), fr = (int)(row & 7), rh = (int)((row >> 3) & 1);
    #pragma unroll
    for (int j = 0; j < 8; j++) {
        float4 wv = ((const float4*)w)[j * 32 + lane];
        int c0 = (j * 32 + lane) * 4;
        int kt = c0 >> 4, kk = c0 & 15, hi = kk >> 3, fc0 = (kk & 7) >> 1;
        size_t wb = ((size_t)(rt * NKT + kt) * 32 + fr * 4 + fc0) * 4 + rh + 2 * hi;
        out[wb]     = pack_h2(v[j].x * s * wv.x, v[j].y * s * wv.y);
        out[wb + 4] = pack_h2(v[j].z * s * wv.z, v[j].w * s * wv.w);
    }
}

// ---------------- fp16 mma.sync GEMM (FM16 inputs) ----------------
// Block 128x128, BK=64 (4 k-tiles), 3-stage cp.async, 4 warps (2x2),
// warp tile 64x64, 2 CTA/SM, single barrier per k-chunk.  (R14-best config)
// resid == null  -> C is fp16 (__half, row-major Nn)
// resid != null  -> C is fp32, C = acc + rs*resid
#define BKK 64
#define STG_WORDS 8192                     // A 4096 + B 4096 uint32
#define GSTG 3
#define GEMM_SMEM (GSTG * STG_WORDS * 4)   // 98304 B

__global__ __launch_bounds__(128, 2) void gemm_tc_kernel(
    int Nn, const uint32_t* __restrict__ A, const uint32_t* __restrict__ Bt,
    void* __restrict__ Cv,
    const float* __restrict__ resid, const float* __restrict__ rs_ptr)
{
    extern __shared__ float sm[];
    const int tid = threadIdx.x, lane = tid & 31, wid = tid >> 5;
    const int mtile = blockIdx.y * 128, ntile = blockIdx.x * 128;
    const int wmt = (wid & 1) * 4;      // A 16-row tile base
    const int wnt = (wid >> 1) * 8;     // B 8-col tile base

    uint32_t smb = smem_u32(sm);

    auto stage_load = [&](int s, int kc) {
        uint32_t as = smb + (uint32_t)s * (STG_WORDS * 4);
        uint32_t bs = as + 4096 * 4;
        #pragma unroll
        for (int rt = 0; rt < 8; rt++)
            cp16(as + (uint32_t)(rt * 2048 + tid * 16),
                 A + (size_t)(blockIdx.y * 8 + rt) * (NKT * 128) + kc * 512 + tid * 4);
        #pragma unroll
        for (int i = 0; i < 8; i++) {
            int nt = i * 2 + (tid >> 6);
            cp16(bs + (uint32_t)(nt * 1024 + (tid & 63) * 16),
                 Bt + (size_t)(blockIdx.x * 16 + nt) * (NKT * 64) + kc * 256 + (tid & 63) * 4);
        }
        cp_commit();
    };

    float acc[4][8][4];
    #pragma unroll
    for (int mi = 0; mi < 4; mi++)
        #pragma unroll
        for (int ni = 0; ni < 8; ni++)
            #pragma unroll
            for (int j = 0; j < 4; j++) acc[mi][ni][j] = 0.f;

    const int NKC = DD / BKK;           // 16
    stage_load(0, 0);
    stage_load(1, 1);

    for (int kc = 0; kc < NKC; kc++) {
        cp_wait1();
        __syncthreads();                 // single barrier per chunk
        if (kc + 2 < NKC) stage_load((kc + 2) % GSTG, kc + 2);
        else cp_commit();

        const uint32_t* sA = (const uint32_t*)sm + (kc % GSTG) * STG_WORDS;
        const uint32_t* sB = sA + 4096;

        #pragma unroll
        for (int kt = 0; kt < 4; kt++) {
            uint32_t a[4][4];
            #pragma unroll
            for (int mi = 0; mi < 4; mi++) {
                uint4 av = *(const uint4*)(sA + (((wmt + mi) * 4 + kt) * 32 + lane) * 4);
                a[mi][0] = av.x; a[mi][1] = av.y; a[mi][2] = av.z; a[mi][3] = av.w;
            }
            #pragma unroll
            for (int ni = 0; ni < 8; ni++) {
                uint2 bv = *(const uint2*)(sB + (((wnt + ni) * 4 + kt) * 32 + lane) * 2);
                #pragma unroll
                for (int mi = 0; mi < 4; mi++)
                    mma_f16(acc[mi][ni], a[mi], bv.x, bv.y);
            }
        }
    }
    cp_wait0();

    // epilogue
    const int fr = lane >> 2, fc = lane & 3;
    const int wm = (wid & 1) * 64, wn = (wid >> 1) * 64;
    if (resid) {
        float* C = (float*)Cv;
        float rs = __ldg(rs_ptr);
        #pragma unroll
        for (int mi = 0; mi < 4; mi++)
            #pragma unroll
            for (int half = 0; half < 2; half++) {
                int row = mtile + wm + mi * 16 + half * 8 + fr;
                #pragma unroll
                for (int ni = 0; ni < 8; ni++) {
                    int col = ntile + wn + ni * 8 + fc * 2;
                    size_t off = (size_t)row * Nn + col;
                    float2 rv = *(const float2*)(resid + off);
                    float2 v = make_float2(fmaf(rs, rv.x, acc[mi][ni][half * 2]),
                                           fmaf(rs, rv.y, acc[mi][ni][half * 2 + 1]));
                    *(float2*)(C + off) = v;
                }
            }
    } else {
        uint32_t* Ch = (uint32_t*)Cv;   // fp16 output, 2 cols per word
        #pragma unroll
        for (int mi = 0; mi < 4; mi++)
            #pragma unroll
            for (int half = 0; half < 2; half++) {
                int row = mtile + wm + mi * 16 + half * 8 + fr;
                #pragma unroll
                for (int ni = 0; ni < 8; ni++) {
                    int col = ntile + wn + ni * 8 + fc * 2;
                    Ch[(size_t)row * (Nn / 2) + col / 2] =
                        pack_h2(acc[mi][ni][half * 2], acc[mi][ni][half * 2 + 1]);
                }
            }
    }
}

// ---------------- scan phase 1: local conv+silu+scan, 2 channels/thread -------
__global__ __launch_bounds__(256) void conv_local_kernel(
    const __half* __restrict__ xz, const float* __restrict__ conv_w,
    const float* __restrict__ conv_b, const float* __restrict__ decay,
    __half* __restrict__ hs, float* __restrict__ last)
{
    int idx = blockIdx.x * blockDim.x + threadIdx.x;   // BB*NCH*DD/2
    int d2 = idx % (DD / 2);                           // pair index
    int ch = (idx / (DD / 2)) % NCH;
    int b  = idx / ((DD / 2) * NCH);
    int d  = d2 * 2;

    float4 cw0 = *(const float4*)(conv_w + d * KW);        // w[d][0..3]
    float4 cw1 = *(const float4*)(conv_w + (d + 1) * KW);  // w[d+1][0..3]
    float2 bias = *(const float2*)(conv_b + d);
    float2 dc   = *(const float2*)(decay + d);
    float aA = __fdividef(1.f, 1.f + __expf(-dc.x));
    float aB = __fdividef(1.f, 1.f + __expf(-dc.y));

    int t0 = ch * LCH;
    const __half2* xb = (const __half2*)(xz + ((size_t)b * SS + t0) * N1) + d2;
    __half2* out = (__half2*)(hs + ((size_t)b * SS + t0) * DD) + d2;

    float x0A = 0.f, x1A = 0.f, x2A = 0.f;
    float x0B = 0.f, x1B = 0.f, x2B = 0.f;
    if (ch > 0) {
        float2 p3 = __half22float2(xb[-3 * (N1 / 2)]);
        float2 p2 = __half22float2(xb[-2 * (N1 / 2)]);
        float2 p1 = __half22float2(xb[-1 * (N1 / 2)]);
        x0A = p3.x; x1A = p2.x; x2A = p1.x;
        x0B = p3.y; x1B = p2.y; x2B = p1.y;
    }
    float hA = 0.f, hB = 0.f;
    #pragma unroll 4
    for (int t = 0; t < LCH; t++) {
        float2 xt = __half22float2(xb[(size_t)t * (N1 / 2)]);
        float cA = fmaf(cw0.x, x0A, fmaf(cw0.y, x1A, fmaf(cw0.z, x2A, fmaf(cw0.w, xt.x, bias.x))));
        float cB = fmaf(cw1.x, x0B, fmaf(cw1.y, x1B, fmaf(cw1.z, x2B, fmaf(cw1.w, xt.y, bias.y))));
        cA = silu_f(cA);
        cB = silu_f(cB);
        hA = fmaf(aA, hA, cA);
        hB = fmaf(aB, hB, cB);
        out[(size_t)t * (DD / 2)] = __floats2half2_rn(hA, hB);
        x0A = x1A; x1A = x2A; x2A = xt.x;
        x0B = x1B; x1B = x2B; x2B = xt.y;
    }
    *(float2*)(last + ((size_t)b * NCH + ch) * DD + d) = make_float2(hA, hB);
}

// ---------------- scan phase 2: carry chain + l2a precompute ----------------
__global__ __launch_bounds__(256) void carry_kernel(
    const float* __restrict__ decay, const float* __restrict__ last,
    float* __restrict__ sin_, float* __restrict__ l2a)
{
    int idx = blockIdx.x * blockDim.x + threadIdx.x;   // BB*DD
    int d = idx % DD, b = idx / DD;
    float a = __fdividef(1.f, 1.f + __expf(-decay[d]));
    if (b == 0) l2a[d] = log2f(a);
    float aL = a;
    #pragma unroll
    for (int i = 0; i < 5; i++) aL *= aL;              // a^32
    float c = 0.f;
    #pragma unroll 4
    for (int j = 0; j < NCH; j++) {
        size_t o = ((size_t)b * NCH + j) * DD + d;
        sin_[o] = c;
        c = fmaf(aL, c, last[o]);
    }
}

// ---------------- gated rmsnorm with fused carry, warp-per-row (FM16 out) -----
__global__ __launch_bounds__(256) void gate_kernel(
    const __half* __restrict__ hs, const float* __restrict__ gate_w,
    const __half* __restrict__ xz, const float* __restrict__ l2a,
    const float* __restrict__ sin_, uint32_t* __restrict__ y)
{
    int warp = threadIdx.x >> 5, lane = threadIdx.x & 31;
    size_t row = (size_t)blockIdx.x * 8 + warp;
    int b = (int)(row / SS);
    int sidx = (int)(row % SS);
    int chk = sidx / LCH, tt = sidx % LCH;
    float tp = (float)(tt + 1);

    const uint2* hr = (const uint2*)(hs + row * DD);
    const float4* sr = (const float4*)(sin_ + ((size_t)b * NCH + chk) * DD);
    const float4* lr = (const float4*)l2a;

    float4 v[8];
    float ss = 0.f;
    #pragma unroll
    for (int j = 0; j < 8; j++) {
        uint2 hw = hr[j * 32 + lane];
        float2 f0 = __half22float2(*(__half2*)&hw.x);
        float2 f1 = __half22float2(*(__half2*)&hw.y);
        float4 sv = sr[j * 32 + lane];
        float4 la = lr[j * 32 + lane];
        v[j].x = f0.x + sv.x * exp2f(tp * la.x);
        v[j].y = f0.y + sv.y * exp2f(tp * la.y);
        v[j].z = f1.x + sv.z * exp2f(tp * la.z);
        v[j].w = f1.y + sv.w * exp2f(tp * la.w);
        ss += v[j].x * v[j].x + v[j].y * v[j].y + v[j].z * v[j].z + v[j].w * v[j].w;
    }
    ss = warp_reduce_sum(ss);
    float s = rsqrtf(ss * (1.f / DD) + EPSV);

    const uint2* zr = (const uint2*)(xz + row * N1 + DD);
    int rt = (int)(row >> 4), fr = (int)(row & 7), rh = (int)((row >> 3) & 1);
    #pragma unroll
    for (int j = 0; j < 8; j++) {
        float4 gw = ((const float4*)gate_w)[j * 32 + lane];
        uint2 zw = zr[j * 32 + lane];
        float2 z0 = __half22float2(*(__half2*)&zw.x);
        float2 z1 = __half22float2(*(__half2*)&zw.y);
        int c0 = (j * 32 + lane) * 4;
        int kt = c0 >> 4, kk = c0 & 15, hi = kk >> 3, fc0 = (kk & 7) >> 1;
        size_t wb = ((size_t)(rt * NKT + kt) * 32 + fr * 4 + fc0) * 4 + rh + 2 * hi;
        y[wb]     = pack_h2(v[j].x * s * gw.x * silu_f(z0.x), v[j].y * s * gw.y * silu_f(z0.y));
        y[wb + 4] = pack_h2(v[j].z * s * gw.z * silu_f(z1.x), v[j].w * s * gw.w * silu_f(z1.y));
    }
}

// ---------------- host ----------------
extern "C" void kernel_launch(void* const* d_in, const int* in_sizes, int n_in,
                              void* d_out, int out_size)
{
    const float* x         = (const float*)d_in[0];
    const float* norm_w    = (const float*)d_in[1];
    const float* in_w      = (const float*)d_in[2];
    const float* conv_w    = (const float*)d_in[3];
    const float* conv_b    = (const float*)d_in[4];
    const float* decay     = (const float*)d_in[5];
    const float* gate_w    = (const float*)d_in[6];
    const float* out_w     = (const float*)d_in[7];
    const float* res_scale = (const float*)d_in[8];
    float* out = (float*)d_out;

    uint32_t *p_h, *p_wt1, *p_wt2;
    __half *p_xz, *p_hs;
    float *p_last, *p_sin, *p_l2a;
    cudaGetSymbolAddress((void**)&p_h,    g_h);
    cudaGetSymbolAddress((void**)&p_xz,   g_xz);
    cudaGetSymbolAddress((void**)&p_hs,   g_hs);
    cudaGetSymbolAddress((void**)&p_wt1,  g_wt1);
    cudaGetSymbolAddress((void**)&p_wt2,  g_wt2);
    cudaGetSymbolAddress((void**)&p_last, g_last);
    cudaGetSymbolAddress((void**)&p_sin,  g_sin);
    cudaGetSymbolAddress((void**)&p_l2a,  g_l2a);

    static bool smem_set = false;
    if (!smem_set) {
        cudaFuncSetAttribute(gemm_tc_kernel,
                             cudaFuncAttributeMaxDynamicSharedMemorySize, GEMM_SMEM);
        smem_set = true;
    }

    // 0. transpose both weights -> fp16 FM16 (one launch)
    transpose_kernel<<<dim3(N1 / 32, DD / 32, 2), 256>>>(
        in_w, (__half*)p_wt1, out_w, (__half*)p_wt2);

    // 1. h = rmsnorm(x) (fp16 FM16), warp-per-row
    rmsnorm_kernel<<<MM / 8, 256>>>(x, norm_w, p_h);

    // 2. xz = h @ in_w  (fp16 output)
    gemm_tc_kernel<<<dim3(N1 / 128, MM / 128), 128, GEMM_SMEM>>>(
        N1, p_h, p_wt1, p_xz, nullptr, nullptr);

    // 3. chunked conv + local scan (LCH=32, 2ch/thread) + carry chain
    conv_local_kernel<<<(BB * NCH * DD / 2) / 256, 256>>>(
        p_xz, conv_w, conv_b, decay, p_hs, p_last);
    carry_kernel<<<(BB * DD) / 256, 256>>>(decay, p_last, p_sin, p_l2a);

    // 4. y = rmsnorm(hs + carry)*silu(z) (fp16 FM16), warp-per-row -> g_h
    gate_kernel<<<MM / 8, 256>>>(p_hs, gate_w, p_xz, p_l2a, p_sin, p_h);

    // 5. out = res_scale*x + y @ out_w  (fp32 + residual)
    gemm_tc_kernel<<<dim3(DD / 128, MM / 128), 128, GEMM_SMEM>>>(
        DD, p_h, p_wt2, out, x, res_scale);
}

// round 17
// speedup vs baseline: 1.1415x; 1.0004x over previous
#include <cuda_runtime.h>
#include <cuda_fp16.h>
#include <math.h>
#include <stdint.h>

// ---------------- problem constants ----------------
#define BB 4
#define SS 4096
#define DD 1024
#define KW 4
#define MM (BB * SS)      // 16384
#define N1 (2 * DD)       // 2048
#define EPSV 1e-6f
#define LCH 32            // scan chunk length
#define NCH (SS / LCH)    // 128
#define NKT (DD / 16)     // 64 fragment k-tiles

// ---------------- scratch (__device__ globals; no allocs) ----------------
__device__ uint32_t g_h  [(size_t)MM * DD / 2];   // rmsnorm(x) / gated y (FM16)
__device__ __half   g_xz [(size_t)MM * N1];       // GEMM1 out (fp16 row-major)
__device__ __half   g_hs [(size_t)MM * DD];       // local scan out (fp16)
__device__ uint32_t g_wt1[(size_t)N1 * DD / 2];   // in_w^T  FM16
__device__ uint32_t g_wt2[(size_t)DD * DD / 2];   // out_w^T FM16
__device__ float g_last[(size_t)BB * NCH * DD];
__device__ float g_sin [(size_t)BB * NCH * DD];
__device__ float g_l2a [DD];                      // log2(sigmoid(decay))

// FM16 A-type X[R][K] (m16n8k16 .row operand), 32-bit words:
//   word = ((rt*(K/16)+kt)*32 + (r&7)*4 + ((k&7)>>1))*4 + ((r>>3)&1) + 2*((k&15)>=8), half=k&1
// FM16 B-type Bt[N][K] (.col operand):
//   word = ((nt*(K/16)+kt)*32 + (n&7)*4 + ((k&7)>>1))*2 + ((k&15)>>3), half=k&1

// ---------------- helpers ----------------
__device__ __forceinline__ float silu_f(float v) {
    return __fdividef(v, 1.f + __expf(-v));
}

__device__ __forceinline__ uint32_t smem_u32(const void* p) {
    uint32_t a;
    asm("{ .reg .u64 t; cvta.to.shared.u64 t, %1; cvt.u32.u64 %0, t; }" : "=r"(a) : "l"(p));
    return a;
}
__device__ __forceinline__ void cp16(uint32_t s, const void* g) {
    asm volatile("cp.async.cg.shared.global [%0], [%1], 16;" :: "r"(s), "l"(g) : "memory");
}
__device__ __forceinline__ void cp_commit() {
    asm volatile("cp.async.commit_group;" ::: "memory");
}
__device__ __forceinline__ void cp_wait1() {
    asm volatile("cp.async.wait_group 1;" ::: "memory");
}
__device__ __forceinline__ void cp_wait0() {
    asm volatile("cp.async.wait_group 0;" ::: "memory");
}

__device__ __forceinline__ void mma_f16(float* c, const uint32_t* a, uint32_t b0, uint32_t b1) {
    asm volatile(
        "mma.sync.aligned.m16n8k16.row.col.f32.f16.f16.f32 "
        "{%0,%1,%2,%3}, {%4,%5,%6,%7}, {%8,%9}, {%0,%1,%2,%3};"
        : "+f"(c[0]), "+f"(c[1]), "+f"(c[2]), "+f"(c[3])
        : "r"(a[0]), "r"(a[1]), "r"(a[2]), "r"(a[3]), "r"(b0), "r"(b1));
}

__device__ __forceinline__ uint32_t pack_h2(float lo, float hi) {
    __half2 h = __floats2half2_rn(lo, hi);
    return *(uint32_t*)&h;
}

__device__ __forceinline__ float warp_reduce_sum(float v) {
    #pragma unroll
    for (int o = 16; o > 0; o >>= 1) v += __shfl_xor_sync(0xffffffffu, v, o);
    return v;
}

// ---------------- weight transpose -> FM16 B layout (both weights, one launch) --
__global__ __launch_bounds__(256) void transpose_kernel(
    const float* __restrict__ in1, __half* __restrict__ out1,
    const float* __restrict__ in2, __half* __restrict__ out2)
{
    const float* in;
    __half* out;
    int Nn;
    if (blockIdx.z == 0) { in = in1; out = out1; Nn = N1; }
    else {
        if (blockIdx.x >= DD / 32) return;
        in = in2; out = out2; Nn = DD;
    }
    __shared__ float tile[32][33];
    int n0 = blockIdx.x * 32, k0 = blockIdx.y * 32;
    int tx = threadIdx.x & 31, ty = threadIdx.x >> 5;
    #pragma unroll
    for (int i = 0; i < 32; i += 8)
        tile[ty + i][tx] = in[(size_t)(k0 + ty + i) * Nn + n0 + tx];
    __syncthreads();
    int k = k0 + tx;
    int kt = k >> 4, kk = k & 15;
    int fc = (kk & 7) >> 1, hi = kk >> 3, lo = kk & 1;
    #pragma unroll
    for (int i = 0; i < 32; i += 8) {
        int n = n0 + ty + i;
        int nt = n >> 3, fn = n & 7;
        size_t hoff = (((size_t)(nt * NKT + kt) * 32 + fn * 4 + fc) * 2 + hi) * 2 + lo;
        out[hoff] = __float2half_rn(tile[tx][ty + i]);
    }
}

// ---------------- rmsnorm, warp-per-row (fp16 FM16 A output) ----------------
__global__ __launch_bounds__(256) void rmsnorm_kernel(
    const float* __restrict__ x, const float* __restrict__ w, uint32_t* __restrict__ out)
{
    int warp = threadIdx.x >> 5, lane = threadIdx.x & 31;
    size_t row = (size_t)blockIdx.x * 8 + warp;
    const float4* xr = (const float4*)(x + row * DD);

    float4 v[8];
    float ss = 0.f;
    #pragma unroll
    for (int j = 0; j < 8; j++) {
        v[j] = xr[j * 32 + lane];
        ss += v[j].x * v[j].x + v[j].y * v[j].y + v[j].z * v[j].z + v[j].w * v[j].w;
    }
    ss = warp_reduce_sum(ss);
    float s = rsqrtf(ss * (1.f / DD) + EPSV);

    int rt = (int)(row >> 4), fr = (int)(row & 7), rh = (int)((row >> 3) & 1);
    #pragma unroll
    for (int j = 0; j < 8; j++) {
        float4 wv = ((const float4*)w)[j * 32 + lane];
        int c0 = (j * 32 + lane) * 4;
        int kt = c0 >> 4, kk = c0 & 15, hi = kk >> 3, fc0 = (kk & 7) >> 1;
        size_t wb = ((size_t)(rt * NKT + kt) * 32 + fr * 4 + fc0) * 4 + rh + 2 * hi;
        out[wb]     = pack_h2(v[j].x * s * wv.x, v[j].y * s * wv.y);
        out[wb + 4] = pack_h2(v[j].z * s * wv.z, v[j].w * s * wv.w);
    }
}

// ---------------- fp16 mma.sync GEMM (FM16 inputs) ----------------
// Block 128x128, BK=64 (4 k-tiles), 3-stage cp.async, 4 warps (2x2),
// warp tile 64x64, 2 CTA/SM, single barrier per k-chunk.
// Fragment double-buffering: prefetch kt+1's fragments while MMAing kt.
// resid == null  -> C is fp16 (__half, row-major Nn)
// resid != null  -> C is fp32, C = acc + rs*resid
#define BKK 64
#define STG_WORDS 8192                     // A 4096 + B 4096 uint32
#define GSTG 3
#define GEMM_SMEM (GSTG * STG_WORDS * 4)   // 98304 B

__global__ __launch_bounds__(128, 2) void gemm_tc_kernel(
    int Nn, const uint32_t* __restrict__ A, const uint32_t* __restrict__ Bt,
    void* __restrict__ Cv,
    const float* __restrict__ resid, const float* __restrict__ rs_ptr)
{
    extern __shared__ float sm[];
    const int tid = threadIdx.x, lane = tid & 31, wid = tid >> 5;
    const int mtile = blockIdx.y * 128, ntile = blockIdx.x * 128;
    const int wmt = (wid & 1) * 4;      // A 16-row tile base
    const int wnt = (wid >> 1) * 8;     // B 8-col tile base

    uint32_t smb = smem_u32(sm);

    auto stage_load = [&](int s, int kc) {
        uint32_t as = smb + (uint32_t)s * (STG_WORDS * 4);
        uint32_t bs = as + 4096 * 4;
        #pragma unroll
        for (int rt = 0; rt < 8; rt++)
            cp16(as + (uint32_t)(rt * 2048 + tid * 16),
                 A + (size_t)(blockIdx.y * 8 + rt) * (NKT * 128) + kc * 512 + tid * 4);
        #pragma unroll
        for (int i = 0; i < 8; i++) {
            int nt = i * 2 + (tid >> 6);
            cp16(bs + (uint32_t)(nt * 1024 + (tid & 63) * 16),
                 Bt + (size_t)(blockIdx.x * 16 + nt) * (NKT * 64) + kc * 256 + (tid & 63) * 4);
        }
        cp_commit();
    };

    float acc[4][8][4];
    #pragma unroll
    for (int mi = 0; mi < 4; mi++)
        #pragma unroll
        for (int ni = 0; ni < 8; ni++)
            #pragma unroll
            for (int j = 0; j < 4; j++) acc[mi][ni][j] = 0.f;

    const int NKC = DD / BKK;           // 16
    stage_load(0, 0);
    stage_load(1, 1);

    uint32_t a[2][4][4];
    uint32_t b[2][8][2];

    for (int kc = 0; kc < NKC; kc++) {
        cp_wait1();
        __syncthreads();                 // single barrier per chunk
        if (kc + 2 < NKC) stage_load((kc + 2) % GSTG, kc + 2);
        else cp_commit();

        const uint32_t* sA = (const uint32_t*)sm + (kc % GSTG) * STG_WORDS;
        const uint32_t* sB = sA + 4096;

        // prime kt = 0
        #pragma unroll
        for (int mi = 0; mi < 4; mi++) {
            uint4 av = *(const uint4*)(sA + (((wmt + mi) * 4) * 32 + lane) * 4);
            a[0][mi][0] = av.x; a[0][mi][1] = av.y; a[0][mi][2] = av.z; a[0][mi][3] = av.w;
        }
        #pragma unroll
        for (int ni = 0; ni < 8; ni++) {
            uint2 bv = *(const uint2*)(sB + (((wnt + ni) * 4) * 32 + lane) * 2);
            b[0][ni][0] = bv.x; b[0][ni][1] = bv.y;
        }

        #pragma unroll
        for (int kt = 0; kt < 4; kt++) {
            const int cur = kt & 1, nxt = cur ^ 1;
            if (kt < 3) {                // prefetch kt+1 while MMAing kt
                #pragma unroll
                for (int mi = 0; mi < 4; mi++) {
                    uint4 av = *(const uint4*)(sA + (((wmt + mi) * 4 + kt + 1) * 32 + lane) * 4);
                    a[nxt][mi][0] = av.x; a[nxt][mi][1] = av.y;
                    a[nxt][mi][2] = av.z; a[nxt][mi][3] = av.w;
                }
                #pragma unroll
                for (int ni = 0; ni < 8; ni++) {
                    uint2 bv = *(const uint2*)(sB + (((wnt + ni) * 4 + kt + 1) * 32 + lane) * 2);
                    b[nxt][ni][0] = bv.x; b[nxt][ni][1] = bv.y;
                }
            }
            #pragma unroll
            for (int ni = 0; ni < 8; ni++)
                #pragma unroll
                for (int mi = 0; mi < 4; mi++)
                    mma_f16(acc[mi][ni], a[cur][mi], b[cur][ni][0], b[cur][ni][1]);
        }
    }
    cp_wait0();

    // epilogue
    const int fr = lane >> 2, fc = lane & 3;
    const int wm = (wid & 1) * 64, wn = (wid >> 1) * 64;
    if (resid) {
        float* C = (float*)Cv;
        float rs = __ldg(rs_ptr);
        #pragma unroll
        for (int mi = 0; mi < 4; mi++)
            #pragma unroll
            for (int half = 0; half < 2; half++) {
                int row = mtile + wm + mi * 16 + half * 8 + fr;
                #pragma unroll
                for (int ni = 0; ni < 8; ni++) {
                    int col = ntile + wn + ni * 8 + fc * 2;
                    size_t off = (size_t)row * Nn + col;
                    float2 rv = *(const float2*)(resid + off);
                    float2 v = make_float2(fmaf(rs, rv.x, acc[mi][ni][half * 2]),
                                           fmaf(rs, rv.y, acc[mi][ni][half * 2 + 1]));
                    *(float2*)(C + off) = v;
                }
            }
    } else {
        uint32_t* Ch = (uint32_t*)Cv;   // fp16 output, 2 cols per word
        #pragma unroll
        for (int mi = 0; mi < 4; mi++)
            #pragma unroll
            for (int half = 0; half < 2; half++) {
                int row = mtile + wm + mi * 16 + half * 8 + fr;
                #pragma unroll
                for (int ni = 0; ni < 8; ni++) {
                    int col = ntile + wn + ni * 8 + fc * 2;
                    Ch[(size_t)row * (Nn / 2) + col / 2] =
                        pack_h2(acc[mi][ni][half * 2], acc[mi][ni][half * 2 + 1]);
                }
            }
    }
}

// ---------------- scan phase 1: local conv+silu+scan, 2 channels/thread -------
__global__ __launch_bounds__(256) void conv_local_kernel(
    const __half* __restrict__ xz, const float* __restrict__ conv_w,
    const float* __restrict__ conv_b, const float* __restrict__ decay,
    __half* __restrict__ hs, float* __restrict__ last)
{
    int idx = blockIdx.x * blockDim.x + threadIdx.x;   // BB*NCH*DD/2
    int d2 = idx % (DD / 2);                           // pair index
    int ch = (idx / (DD / 2)) % NCH;
    int b  = idx / ((DD / 2) * NCH);
    int d  = d2 * 2;

    float4 cw0 = *(const float4*)(conv_w + d * KW);        // w[d][0..3]
    float4 cw1 = *(const float4*)(conv_w + (d + 1) * KW);  // w[d+1][0..3]
    float2 bias = *(const float2*)(conv_b + d);
    float2 dc   = *(const float2*)(decay + d);
    float aA = __fdividef(1.f, 1.f + __expf(-dc.x));
    float aB = __fdividef(1.f, 1.f + __expf(-dc.y));

    int t0 = ch * LCH;
    const __half2* xb = (const __half2*)(xz + ((size_t)b * SS + t0) * N1) + d2;
    __half2* out = (__half2*)(hs + ((size_t)b * SS + t0) * DD) + d2;

    float x0A = 0.f, x1A = 0.f, x2A = 0.f;
    float x0B = 0.f, x1B = 0.f, x2B = 0.f;
    if (ch > 0) {
        float2 p3 = __half22float2(xb[-3 * (N1 / 2)]);
        float2 p2 = __half22float2(xb[-2 * (N1 / 2)]);
        float2 p1 = __half22float2(xb[-1 * (N1 / 2)]);
        x0A = p3.x; x1A = p2.x; x2A = p1.x;
        x0B = p3.y; x1B = p2.y; x2B = p1.y;
    }
    float hA = 0.f, hB = 0.f;
    #pragma unroll 4
    for (int t = 0; t < LCH; t++) {
        float2 xt = __half22float2(xb[(size_t)t * (N1 / 2)]);
        float cA = fmaf(cw0.x, x0A, fmaf(cw0.y, x1A, fmaf(cw0.z, x2A, fmaf(cw0.w, xt.x, bias.x))));
        float cB = fmaf(cw1.x, x0B, fmaf(cw1.y, x1B, fmaf(cw1.z, x2B, fmaf(cw1.w, xt.y, bias.y))));
        cA = silu_f(cA);
        cB = silu_f(cB);
        hA = fmaf(aA, hA, cA);
        hB = fmaf(aB, hB, cB);
        out[(size_t)t * (DD / 2)] = __floats2half2_rn(hA, hB);
        x0A = x1A; x1A = x2A; x2A = xt.x;
        x0B = x1B; x1B = x2B; x2B = xt.y;
    }
    *(float2*)(last + ((size_t)b * NCH + ch) * DD + d) = make_float2(hA, hB);
}

// ---------------- scan phase 2: carry chain + l2a precompute ----------------
__global__ __launch_bounds__(256) void carry_kernel(
    const float* __restrict__ decay, const float* __restrict__ last,
    float* __restrict__ sin_, float* __restrict__ l2a)
{
    int idx = blockIdx.x * blockDim.x + threadIdx.x;   // BB*DD
    int d = idx % DD, b = idx / DD;
    float a = __fdividef(1.f, 1.f + __expf(-decay[d]));
    if (b == 0) l2a[d] = log2f(a);
    float aL = a;
    #pragma unroll
    for (int i = 0; i < 5; i++) aL *= aL;              // a^32
    float c = 0.f;
    #pragma unroll 4
    for (int j = 0; j < NCH; j++) {
        size_t o = ((size_t)b * NCH + j) * DD + d;
        sin_[o] = c;
        c = fmaf(aL, c, last[o]);
    }
}

// ---------------- gated rmsnorm with fused carry, warp-per-row (FM16 out) -----
__global__ __launch_bounds__(256) void gate_kernel(
    const __half* __restrict__ hs, const float* __restrict__ gate_w,
    const __half* __restrict__ xz, const float* __restrict__ l2a,
    const float* __restrict__ sin_, uint32_t* __restrict__ y)
{
    int warp = threadIdx.x >> 5, lane = threadIdx.x & 31;
    size_t row = (size_t)blockIdx.x * 8 + warp;
    int b = (int)(row / SS);
    int sidx = (int)(row % SS);
    int chk = sidx / LCH, tt = sidx % LCH;
    float tp = (float)(tt + 1);

    const uint2* hr = (const uint2*)(hs + row * DD);
    const float4* sr = (const float4*)(sin_ + ((size_t)b * NCH + chk) * DD);
    const float4* lr = (const float4*)l2a;

    float4 v[8];
    float ss = 0.f;
    #pragma unroll
    for (int j = 0; j < 8; j++) {
        uint2 hw = hr[j * 32 + lane];
        float2 f0 = __half22float2(*(__half2*)&hw.x);
        float2 f1 = __half22float2(*(__half2*)&hw.y);
        float4 sv = sr[j * 32 + lane];
        float4 la = lr[j * 32 + lane];
        v[j].x = f0.x + sv.x * exp2f(tp * la.x);
        v[j].y = f0.y + sv.y * exp2f(tp * la.y);
        v[j].z = f1.x + sv.z * exp2f(tp * la.z);
        v[j].w = f1.y + sv.w * exp2f(tp * la.w);
        ss += v[j].x * v[j].x + v[j].y * v[j].y + v[j].z * v[j].z + v[j].w * v[j].w;
    }
    ss = warp_reduce_sum(ss);
    float s = rsqrtf(ss * (1.f / DD) + EPSV);

    const uint2* zr = (const uint2*)(xz + row * N1 + DD);
    int rt = (int)(row >> 4), fr = (int)(row & 7), rh = (int)((row >> 3) & 1);
    #pragma unroll
    for (int j = 0; j < 8; j++) {
        float4 gw = ((const float4*)gate_w)[j * 32 + lane];
        uint2 zw = zr[j * 32 + lane];
        float2 z0 = __half22float2(*(__half2*)&zw.x);
        float2 z1 = __half22float2(*(__half2*)&zw.y);
        int c0 = (j * 32 + lane) * 4;
        int kt = c0 >> 4, kk = c0 & 15, hi = kk >> 3, fc0 = (kk & 7) >> 1;
        size_t wb = ((size_t)(rt * NKT + kt) * 32 + fr * 4 + fc0) * 4 + rh + 2 * hi;
        y[wb]     = pack_h2(v[j].x * s * gw.x * silu_f(z0.x), v[j].y * s * gw.y * silu_f(z0.y));
        y[wb + 4] = pack_h2(v[j].z * s * gw.z * silu_f(z1.x), v[j].w * s * gw.w * silu_f(z1.y));
    }
}

// ---------------- host ----------------
extern "C" void kernel_launch(void* const* d_in, const int* in_sizes, int n_in,
                              void* d_out, int out_size)
{
    const float* x         = (const float*)d_in[0];
    const float* norm_w    = (const float*)d_in[1];
    const float* in_w      = (const float*)d_in[2];
    const float* conv_w    = (const float*)d_in[3];
    const float* conv_b    = (const float*)d_in[4];
    const float* decay     = (const float*)d_in[5];
    const float* gate_w    = (const float*)d_in[6];
    const float* out_w     = (const float*)d_in[7];
    const float* res_scale = (const float*)d_in[8];
    float* out = (float*)d_out;

    uint32_t *p_h, *p_wt1, *p_wt2;
    __half *p_xz, *p_hs;
    float *p_last, *p_sin, *p_l2a;
    cudaGetSymbolAddress((void**)&p_h,    g_h);
    cudaGetSymbolAddress((void**)&p_xz,   g_xz);
    cudaGetSymbolAddress((void**)&p_hs,   g_hs);
    cudaGetSymbolAddress((void**)&p_wt1,  g_wt1);
    cudaGetSymbolAddress((void**)&p_wt2,  g_wt2);
    cudaGetSymbolAddress((void**)&p_last, g_last);
    cudaGetSymbolAddress((void**)&p_sin,  g_sin);
    cudaGetSymbolAddress((void**)&p_l2a,  g_l2a);

    static bool smem_set = false;
    if (!smem_set) {
        cudaFuncSetAttribute(gemm_tc_kernel,
                             cudaFuncAttributeMaxDynamicSharedMemorySize, GEMM_SMEM);
        smem_set = true;
    }

    // 0. transpose both weights -> fp16 FM16 (one launch)
    transpose_kernel<<<dim3(N1 / 32, DD / 32, 2), 256>>>(
        in_w, (__half*)p_wt1, out_w, (__half*)p_wt2);

    // 1. h = rmsnorm(x) (fp16 FM16), warp-per-row
    rmsnorm_kernel<<<MM / 8, 256>>>(x, norm_w, p_h);

    // 2. xz = h @ in_w  (fp16 output)
    gemm_tc_kernel<<<dim3(N1 / 128, MM / 128), 128, GEMM_SMEM>>>(
        N1, p_h, p_wt1, p_xz, nullptr, nullptr);

    // 3. chunked conv + local scan (LCH=32, 2ch/thread) + carry chain
    conv_local_kernel<<<(BB * NCH * DD / 2) / 256, 256>>>(
        p_xz, conv_w, conv_b, decay, p_hs, p_last);
    carry_kernel<<<(BB * DD) / 256, 256>>>(decay, p_last, p_sin, p_l2a);

    // 4. y = rmsnorm(hs + carry)*silu(z) (fp16 FM16), warp-per-row -> g_h
    gate_kernel<<<MM / 8, 256>>>(p_hs, gate_w, p_xz, p_l2a, p_sin, p_h);

    // 5. out = res_scale*x + y @ out_w  (fp32 + residual)
    gemm_tc_kernel<<<dim3(DD / 128, MM / 128), 128, GEMM_SMEM>>>(
        DD, p_h, p_wt2, out, x, res_scale);
}